// round 2
// baseline (speedup 1.0000x reference)
#include <cuda_runtime.h>
#include <cstdint>

// 2-layer LSTM (H=8), B=4096, T=512, then FC(8->4) on last h2.
// Parallelization: 8 lanes per batch element; lane j owns hidden unit j of
// BOTH layers and computes its 4 gates (i,f,g,o) per layer. Weights live in
// registers. Inter-lane h exchange via width-8 warp shuffles.

#define FULLMASK 0xffffffffu
static constexpr int T_LEN = 512;
static constexpr int HID = 8;

// Accurate-enough fast activations: ex2.approx + rcp.approx (~1e-7 rel err),
// MUFU pressure (20/step) stays below the FMA-pipe bound so accuracy is free.
__device__ __forceinline__ float fsig(float x) {
    float e, r;
    asm("ex2.approx.ftz.f32 %0, %1;" : "=f"(e) : "f"(x * -1.4426950408889634f));
    asm("rcp.approx.ftz.f32 %0, %1;" : "=f"(r) : "f"(1.0f + e));
    return r;
}
__device__ __forceinline__ float ftanh(float x) {
    // tanh(x) = 2/(1+e^{-2x}) - 1
    float e, r;
    asm("ex2.approx.ftz.f32 %0, %1;" : "=f"(e) : "f"(x * -2.8853900817779268f));
    asm("rcp.approx.ftz.f32 %0, %1;" : "=f"(r) : "f"(1.0f + e));
    return fmaf(2.0f, r, -1.0f);
}

__global__ __launch_bounds__(32, 8)
void lstm2_kernel(
    const float* __restrict__ x,
    const float* __restrict__ W_ih1, const float* __restrict__ W_hh1,
    const float* __restrict__ b_ih1, const float* __restrict__ b_hh1,
    const float* __restrict__ W_ih2, const float* __restrict__ W_hh2,
    const float* __restrict__ b_ih2, const float* __restrict__ b_hh2,
    const float* __restrict__ W_fc,  const float* __restrict__ b_fc,
    float* __restrict__ out, int B)
{
    const int tid  = blockIdx.x * blockDim.x + threadIdx.x;
    const int elem = tid >> 3;     // batch element
    const int j    = tid & 7;      // hidden unit owned by this lane
    if (elem >= B) return;

    // ---- Load per-thread weights into registers ----
    // Gate g of unit j lives at row r = g*8 + j of each [4H, *] matrix.
    float whh1[4][8], wih2[4][8], whh2[4][8];
    float wih1[4], bias1[4], bias2[4];
#pragma unroll
    for (int g = 0; g < 4; g++) {
        const int r = g * HID + j;
        wih1[g]  = W_ih1[r];
        bias1[g] = b_ih1[r] + b_hh1[r];
        bias2[g] = b_ih2[r] + b_hh2[r];
#pragma unroll
        for (int k = 0; k < 8; k++) {
            whh1[g][k] = W_hh1[r * 8 + k];
            wih2[g][k] = W_ih2[r * 8 + k];
            whh2[g][k] = W_hh2[r * 8 + k];
        }
    }

    float h1 = 0.f, c1 = 0.f, h2 = 0.f, c2 = 0.f;
    float A[8];                    // broadcast h1 (current) across the 8-group
#pragma unroll
    for (int k = 0; k < 8; k++) A[k] = 0.f;

    const float4* xp = reinterpret_cast<const float4*>(x + (size_t)elem * T_LEN);
    float4 xv = xp[0];             // prefetch first chunk

    for (int t4 = 0; t4 < T_LEN / 4; t4++) {
        const float4 xc = xv;
        if (t4 + 1 < T_LEN / 4) xv = xp[t4 + 1];   // prefetch next chunk

#pragma unroll
        for (int u = 0; u < 4; u++) {
            const float xt = (u == 0) ? xc.x : (u == 1) ? xc.y : (u == 2) ? xc.z : xc.w;

            // ---------- layer 1 ----------
            float g0 = fmaf(xt, wih1[0], bias1[0]);
            float g1 = fmaf(xt, wih1[1], bias1[1]);
            float g2 = fmaf(xt, wih1[2], bias1[2]);
            float g3 = fmaf(xt, wih1[3], bias1[3]);
#pragma unroll
            for (int k = 0; k < 8; k++) {
                g0 = fmaf(whh1[0][k], A[k], g0);
                g1 = fmaf(whh1[1][k], A[k], g1);
                g2 = fmaf(whh1[2][k], A[k], g2);
                g3 = fmaf(whh1[3][k], A[k], g3);
            }
            const float i1 = fsig(g0);
            const float f1 = fsig(g1);
            const float gg1 = ftanh(g2);
            const float o1 = fsig(g3);
            c1 = fmaf(f1, c1, i1 * gg1);
            h1 = o1 * ftanh(c1);

            // broadcast new h1 (reused by next step's layer1) and old h2
            float Bv[8];
#pragma unroll
            for (int k = 0; k < 8; k++) {
                A[k]  = __shfl_sync(FULLMASK, h1, k, 8);
                Bv[k] = __shfl_sync(FULLMASK, h2, k, 8);
            }

            // ---------- layer 2 ----------
            float q0 = bias2[0], q1 = bias2[1], q2 = bias2[2], q3 = bias2[3];
#pragma unroll
            for (int k = 0; k < 8; k++) {
                q0 = fmaf(wih2[0][k], A[k], q0);
                q1 = fmaf(wih2[1][k], A[k], q1);
                q2 = fmaf(wih2[2][k], A[k], q2);
                q3 = fmaf(wih2[3][k], A[k], q3);
            }
#pragma unroll
            for (int k = 0; k < 8; k++) {
                q0 = fmaf(whh2[0][k], Bv[k], q0);
                q1 = fmaf(whh2[1][k], Bv[k], q1);
                q2 = fmaf(whh2[2][k], Bv[k], q2);
                q3 = fmaf(whh2[3][k], Bv[k], q3);
            }
            const float i2 = fsig(q0);
            const float f2 = fsig(q1);
            const float gg2 = ftanh(q2);
            const float o2 = fsig(q3);
            c2 = fmaf(f2, c2, i2 * gg2);
            h2 = o2 * ftanh(c2);
        }
    }

    // ---- FC: out[elem][m] = b_fc[m] + sum_k W_fc[m][k] * h2[k], m=0..3 ----
    float Hv[8];
#pragma unroll
    for (int k = 0; k < 8; k++) Hv[k] = __shfl_sync(FULLMASK, h2, k, 8);
    if (j < 4) {
        float acc = b_fc[j];
#pragma unroll
        for (int k = 0; k < 8; k++) acc = fmaf(W_fc[j * 8 + k], Hv[k], acc);
        out[(size_t)elem * 4 + j] = acc;
    }
}

extern "C" void kernel_launch(void* const* d_in, const int* in_sizes, int n_in,
                              void* d_out, int out_size)
{
    const float* x     = (const float*)d_in[0];
    const float* W_ih1 = (const float*)d_in[1];
    const float* W_hh1 = (const float*)d_in[2];
    const float* b_ih1 = (const float*)d_in[3];
    const float* b_hh1 = (const float*)d_in[4];
    const float* W_ih2 = (const float*)d_in[5];
    const float* W_hh2 = (const float*)d_in[6];
    const float* b_ih2 = (const float*)d_in[7];
    const float* b_hh2 = (const float*)d_in[8];
    const float* W_fc  = (const float*)d_in[9];
    const float* b_fc  = (const float*)d_in[10];
    float* out = (float*)d_out;

    const int B = in_sizes[0] / T_LEN;        // 4096
    const int threads = B * HID;              // 8 lanes per element
    const int block = 32;                     // 1 warp/CTA: best wave balance
    const int grid = (threads + block - 1) / block;

    lstm2_kernel<<<grid, block>>>(x, W_ih1, W_hh1, b_ih1, b_hh1,
                                  W_ih2, W_hh2, b_ih2, b_hh2,
                                  W_fc, b_fc, out, B);
}

// round 3
// speedup vs baseline: 1.0002x; 1.0002x over previous
#include <cuda_runtime.h>
#include <cstdint>

// 2-layer LSTM (H=8), B=4096, T=512, then FC(8->4) on last h2.
// Parallelization: 8 lanes per batch element; lane j owns hidden unit j of
// BOTH layers and computes its 4 gates (i,f,g,o) per layer. Weights live in
// registers. Inter-lane h exchange via width-8 warp shuffles.

#define FULLMASK 0xffffffffu
static constexpr int T_LEN = 512;
static constexpr int HID = 8;

// Accurate-enough fast activations: ex2.approx + rcp.approx (~1e-7 rel err),
// MUFU pressure (20/step) stays below the FMA-pipe bound so accuracy is free.
__device__ __forceinline__ float fsig(float x) {
    float e, r;
    asm("ex2.approx.ftz.f32 %0, %1;" : "=f"(e) : "f"(x * -1.4426950408889634f));
    asm("rcp.approx.ftz.f32 %0, %1;" : "=f"(r) : "f"(1.0f + e));
    return r;
}
__device__ __forceinline__ float ftanh(float x) {
    // tanh(x) = 2/(1+e^{-2x}) - 1
    float e, r;
    asm("ex2.approx.ftz.f32 %0, %1;" : "=f"(e) : "f"(x * -2.8853900817779268f));
    asm("rcp.approx.ftz.f32 %0, %1;" : "=f"(r) : "f"(1.0f + e));
    return fmaf(2.0f, r, -1.0f);
}

__global__ __launch_bounds__(32, 8)
void lstm2_kernel(
    const float* __restrict__ x,
    const float* __restrict__ W_ih1, const float* __restrict__ W_hh1,
    const float* __restrict__ b_ih1, const float* __restrict__ b_hh1,
    const float* __restrict__ W_ih2, const float* __restrict__ W_hh2,
    const float* __restrict__ b_ih2, const float* __restrict__ b_hh2,
    const float* __restrict__ W_fc,  const float* __restrict__ b_fc,
    float* __restrict__ out, int B)
{
    const int tid  = blockIdx.x * blockDim.x + threadIdx.x;
    const int elem = tid >> 3;     // batch element
    const int j    = tid & 7;      // hidden unit owned by this lane
    if (elem >= B) return;

    // ---- Load per-thread weights into registers ----
    // Gate g of unit j lives at row r = g*8 + j of each [4H, *] matrix.
    float whh1[4][8], wih2[4][8], whh2[4][8];
    float wih1[4], bias1[4], bias2[4];
#pragma unroll
    for (int g = 0; g < 4; g++) {
        const int r = g * HID + j;
        wih1[g]  = W_ih1[r];
        bias1[g] = b_ih1[r] + b_hh1[r];
        bias2[g] = b_ih2[r] + b_hh2[r];
#pragma unroll
        for (int k = 0; k < 8; k++) {
            whh1[g][k] = W_hh1[r * 8 + k];
            wih2[g][k] = W_ih2[r * 8 + k];
            whh2[g][k] = W_hh2[r * 8 + k];
        }
    }

    float h1 = 0.f, c1 = 0.f, h2 = 0.f, c2 = 0.f;
    float A[8];                    // broadcast h1 (current) across the 8-group
#pragma unroll
    for (int k = 0; k < 8; k++) A[k] = 0.f;

    const float4* xp = reinterpret_cast<const float4*>(x + (size_t)elem * T_LEN);
    float4 xv = xp[0];             // prefetch first chunk

    for (int t4 = 0; t4 < T_LEN / 4; t4++) {
        const float4 xc = xv;
        if (t4 + 1 < T_LEN / 4) xv = xp[t4 + 1];   // prefetch next chunk

#pragma unroll
        for (int u = 0; u < 4; u++) {
            const float xt = (u == 0) ? xc.x : (u == 1) ? xc.y : (u == 2) ? xc.z : xc.w;

            // ---------- layer 1 ----------
            float g0 = fmaf(xt, wih1[0], bias1[0]);
            float g1 = fmaf(xt, wih1[1], bias1[1]);
            float g2 = fmaf(xt, wih1[2], bias1[2]);
            float g3 = fmaf(xt, wih1[3], bias1[3]);
#pragma unroll
            for (int k = 0; k < 8; k++) {
                g0 = fmaf(whh1[0][k], A[k], g0);
                g1 = fmaf(whh1[1][k], A[k], g1);
                g2 = fmaf(whh1[2][k], A[k], g2);
                g3 = fmaf(whh1[3][k], A[k], g3);
            }
            const float i1 = fsig(g0);
            const float f1 = fsig(g1);
            const float gg1 = ftanh(g2);
            const float o1 = fsig(g3);
            c1 = fmaf(f1, c1, i1 * gg1);
            h1 = o1 * ftanh(c1);

            // broadcast new h1 (reused by next step's layer1) and old h2
            float Bv[8];
#pragma unroll
            for (int k = 0; k < 8; k++) {
                A[k]  = __shfl_sync(FULLMASK, h1, k, 8);
                Bv[k] = __shfl_sync(FULLMASK, h2, k, 8);
            }

            // ---------- layer 2 ----------
            float q0 = bias2[0], q1 = bias2[1], q2 = bias2[2], q3 = bias2[3];
#pragma unroll
            for (int k = 0; k < 8; k++) {
                q0 = fmaf(wih2[0][k], A[k], q0);
                q1 = fmaf(wih2[1][k], A[k], q1);
                q2 = fmaf(wih2[2][k], A[k], q2);
                q3 = fmaf(wih2[3][k], A[k], q3);
            }
#pragma unroll
            for (int k = 0; k < 8; k++) {
                q0 = fmaf(whh2[0][k], Bv[k], q0);
                q1 = fmaf(whh2[1][k], Bv[k], q1);
                q2 = fmaf(whh2[2][k], Bv[k], q2);
                q3 = fmaf(whh2[3][k], Bv[k], q3);
            }
            const float i2 = fsig(q0);
            const float f2 = fsig(q1);
            const float gg2 = ftanh(q2);
            const float o2 = fsig(q3);
            c2 = fmaf(f2, c2, i2 * gg2);
            h2 = o2 * ftanh(c2);
        }
    }

    // ---- FC: out[elem][m] = b_fc[m] + sum_k W_fc[m][k] * h2[k], m=0..3 ----
    float Hv[8];
#pragma unroll
    for (int k = 0; k < 8; k++) Hv[k] = __shfl_sync(FULLMASK, h2, k, 8);
    if (j < 4) {
        float acc = b_fc[j];
#pragma unroll
        for (int k = 0; k < 8; k++) acc = fmaf(W_fc[j * 8 + k], Hv[k], acc);
        out[(size_t)elem * 4 + j] = acc;
    }
}

extern "C" void kernel_launch(void* const* d_in, const int* in_sizes, int n_in,
                              void* d_out, int out_size)
{
    const float* x     = (const float*)d_in[0];
    const float* W_ih1 = (const float*)d_in[1];
    const float* W_hh1 = (const float*)d_in[2];
    const float* b_ih1 = (const float*)d_in[3];
    const float* b_hh1 = (const float*)d_in[4];
    const float* W_ih2 = (const float*)d_in[5];
    const float* W_hh2 = (const float*)d_in[6];
    const float* b_ih2 = (const float*)d_in[7];
    const float* b_hh2 = (const float*)d_in[8];
    const float* W_fc  = (const float*)d_in[9];
    const float* b_fc  = (const float*)d_in[10];
    float* out = (float*)d_out;

    const int B = in_sizes[0] / T_LEN;        // 4096
    const int threads = B * HID;              // 8 lanes per element
    const int block = 32;                     // 1 warp/CTA: best wave balance
    const int grid = (threads + block - 1) / block;

    lstm2_kernel<<<grid, block>>>(x, W_ih1, W_hh1, b_ih1, b_hh1,
                                  W_ih2, W_hh2, b_ih2, b_hh2,
                                  W_fc, b_fc, out, B);
}